// round 4
// baseline (speedup 1.0000x reference)
#include <cuda_runtime.h>
#include <math.h>

typedef unsigned long long ull;

#define BQ 8
#define HWQ 60800
#define NQ 182400          // 3*200*304
#define SL 57
#define CH4 800            // 57*800 = 45600 float4 per batch
#define KQ 2000
#define CAP 4096
#define NBIN 4096
#define LOG_MAX_F 4.1351665567423560f
#define IMG_W 1216.0f
#define IMG_H 800.0f
#define OFF_SCORES 64000
#define OFF_KEEP   80000

// ---------------- device scratch ----------------
__device__ unsigned g_h[BQ][NBIN];        // 12-bit histogram (zeroed at end of k_apply)
__device__ unsigned g_S[BQ][NBIN + 1];    // suffix counts S[v] = #elems with bin >= v
__device__ unsigned g_cur[BQ][NBIN];      // per-bin scatter cursors (zeroed in k_thr)
__device__ int      g_B[BQ];              // threshold bin
__device__ ull      g_cand[BQ][CAP];      // bin-grouped candidates
__device__ float4   g_boxes[BQ][KQ];      // decoded boxes by rank
__device__ unsigned char g_valid[BQ][2048]; // [2000..2048) stays zero forever
__device__ unsigned g_adjT[BQ][64][2048]; // suppression matrix, column(word)-major

__device__ __forceinline__ unsigned fkey(float f) {
    unsigned u = __float_as_uint(f);
    return (u & 0x80000000u) ? ~u : (u | 0x80000000u);
}
__device__ __forceinline__ float unkey(unsigned u) {
    unsigned b = (u & 0x80000000u) ? (u & 0x7fffffffu) : ~u;
    return __uint_as_float(b);
}

// ================ K1: 12-bit histogram ================
__global__ __launch_bounds__(256) void k_hist(const float* __restrict__ cls) {
    const int s = blockIdx.x, b = blockIdx.y, tid = threadIdx.x;
    __shared__ unsigned h[NBIN];
    for (int i = tid; i < NBIN; i += 256) h[i] = 0u;
    __syncthreads();
    const float4* p4 = (const float4*)(cls + (size_t)b * NQ);
    for (int q4 = s * CH4 + tid; q4 < (s + 1) * CH4; q4 += 256) {
        float4 v = p4[q4];
        atomicAdd(&h[fkey(v.x) >> 20], 1u);
        atomicAdd(&h[fkey(v.y) >> 20], 1u);
        atomicAdd(&h[fkey(v.z) >> 20], 1u);
        atomicAdd(&h[fkey(v.w) >> 20], 1u);
    }
    __syncthreads();
    for (int i = tid; i < NBIN; i += 256)
        if (h[i]) atomicAdd(&g_h[b][i], h[i]);
}

// ================ K2: suffix counts + threshold bin + zero cursors ================
__global__ __launch_bounds__(1024) void k_thr() {
    const int b = blockIdx.x, tid = threadIdx.x;
    __shared__ unsigned sT[1024];
    __shared__ int sB;
    unsigned c0 = g_h[b][4 * tid + 0];
    unsigned c1 = g_h[b][4 * tid + 1];
    unsigned c2 = g_h[b][4 * tid + 2];
    unsigned c3 = g_h[b][4 * tid + 3];
    unsigned s3 = c3, s2 = c2 + s3, s1 = c1 + s2, s0 = c0 + s1;
    sT[tid] = s0;
    if (tid == 0) sB = 0;
    __syncthreads();
    for (int ofs = 1; ofs < 1024; ofs <<= 1) {
        unsigned u = (tid + ofs < 1024) ? sT[tid + ofs] : 0u;
        __syncthreads();
        sT[tid] += u;
        __syncthreads();
    }
    unsigned suf = sT[tid] - s0;   // sum over threads > tid
    unsigned S0 = s0 + suf, S1 = s1 + suf, S2 = s2 + suf, S3 = s3 + suf;
    g_S[b][4 * tid + 0] = S0;
    g_S[b][4 * tid + 1] = S1;
    g_S[b][4 * tid + 2] = S2;
    g_S[b][4 * tid + 3] = S3;
    if (tid == 0) g_S[b][NBIN] = 0u;
    int best = -1;
    if (S3 >= (unsigned)KQ) best = 4 * tid + 3;
    else if (S2 >= (unsigned)KQ) best = 4 * tid + 2;
    else if (S1 >= (unsigned)KQ) best = 4 * tid + 1;
    else if (S0 >= (unsigned)KQ) best = 4 * tid + 0;
    if (best >= 0) atomicMax(&sB, best);
    // zero cursors for K3
    g_cur[b][4 * tid + 0] = 0u;
    g_cur[b][4 * tid + 1] = 0u;
    g_cur[b][4 * tid + 2] = 0u;
    g_cur[b][4 * tid + 3] = 0u;
    __syncthreads();
    if (tid == 0) g_B[b] = sB;
}

// ================ K3: bin-scatter compaction ================
__global__ __launch_bounds__(256) void k_compact(const float* __restrict__ cls) {
    const int s = blockIdx.x, b = blockIdx.y, tid = threadIdx.x;
    const unsigned B = (unsigned)g_B[b];
    const float4* p4 = (const float4*)(cls + (size_t)b * NQ);
    for (int q4 = s * CH4 + tid; q4 < (s + 1) * CH4; q4 += 256) {
        float4 v = p4[q4];
        float vv[4] = {v.x, v.y, v.z, v.w};
        #pragma unroll
        for (int c = 0; c < 4; c++) {
            unsigned u = fkey(vv[c]);
            unsigned bin = u >> 20;
            if (bin >= B) {
                int q = q4 * 4 + c;
                int a = q / HWQ;
                int hw = q - a * HWQ;
                unsigned m = (unsigned)(hw * 3 + a);
                unsigned pos = g_S[b][bin + 1] + atomicAdd(&g_cur[b][bin], 1u);
                if (pos < CAP) g_cand[b][pos] = ((ull)u << 32) | (~m);
            }
        }
    }
}

// ================ K4: exact ranks + decode ================
__global__ __launch_bounds__(1024, 1) void k_rankdec(const float* __restrict__ regs,
                                                     float* __restrict__ dout) {
    __shared__ ull sc[CAP];
    const int b = blockIdx.x, tid = threadIdx.x;
    const int B = g_B[b];
    int n = (int)g_S[b][B];
    if (n > CAP) n = CAP;
    for (int i = tid; i < n; i += 1024) sc[i] = g_cand[b][i];
    __syncthreads();

    for (int i = tid; i < n; i += 1024) {
        ull pk = sc[i];
        unsigned bin = (unsigned)(pk >> 52);
        int lo = (int)g_S[b][bin + 1];
        int hi = (int)g_S[b][bin];
        if (hi > n) hi = n;
        int cnt = 0;
        for (int t = lo; t < hi; t++) cnt += (sc[t] > pk);
        int r = lo + cnt;
        if (r < KQ) {
            unsigned u = (unsigned)(pk >> 32);
            int m = (int)(~(unsigned)pk);
            dout[OFF_SCORES + b * KQ + r] = unkey(u);

            int a = m % 3, hw = m / 3;
            const float* base = regs + ((size_t)b * 12 + 4 * a) * HWQ + hw;
            float dx = base[0];
            float dy = base[HWQ];
            float dh = base[2 * HWQ];
            float dw = base[3 * HWQ];
            float sA = (float)(32 << a);
            float cc = __fmul_rn(sA, 0.5f);
            float px = __fadd_rn(cc, __fmul_rn(dx, sA));
            float py = __fadd_rn(cc, __fmul_rn(dy, sA));
            float ph = __fmul_rn(expf(fminf(dh, LOG_MAX_F)), sA);
            float pw = __fmul_rn(expf(fminf(dw, LOG_MAX_F)), sA);
            float hw2 = __fmul_rn(pw, 0.5f);
            float hh2 = __fmul_rn(ph, 0.5f);
            float x1 = __fsub_rn(px, hw2);
            float y1 = __fsub_rn(py, hh2);
            float x2 = __fadd_rn(px, hw2);
            float y2 = __fadd_rn(py, hh2);
            float bw = __fsub_rn(fminf(fmaxf(x2, 0.0f), IMG_W), fminf(fmaxf(x1, 0.0f), IMG_W));
            float bh = __fsub_rn(fminf(fmaxf(y2, 0.0f), IMG_H), fminf(fmaxf(y1, 0.0f), IMG_H));
            g_valid[b][r] = (bw >= 16.0f && bh >= 16.0f) ? 1 : 0;
            g_boxes[b][r] = make_float4(x1, y1, x2, y2);
        }
    }
}

// ================ K5: suppression matrix (column-major) ================
__global__ __launch_bounds__(256) void k_adj() {
    const int w = blockIdx.x, b = blockIdx.y, tid = threadIdx.x;
    __shared__ float bx1[2048], by1[2048], bx2[2048], by2[2048], bar[2048];
    for (int i = tid; i < 2048; i += 256) {
        float4 v = (i < KQ) ? g_boxes[b][i] : make_float4(0.f, 0.f, 0.f, 0.f);
        bx1[i] = v.x; by1[i] = v.y; bx2[i] = v.z; by2[i] = v.w;
        bar[i] = __fmul_rn(__fsub_rn(v.z, v.x), __fsub_rn(v.w, v.y));
    }
    __syncthreads();

    float rx1[8], ry1[8], rx2[8], ry2[8], rar[8];
    unsigned bits[8];
    int rows[8];
    #pragma unroll
    for (int r = 0; r < 8; r++) {
        int i = tid + 256 * r;
        rows[r] = i;
        rx1[r] = bx1[i]; ry1[r] = by1[i]; rx2[r] = bx2[i]; ry2[r] = by2[i]; rar[r] = bar[i];
        bits[r] = 0u;
    }
    #pragma unroll
    for (int jj = 0; jj < 32; jj++) {
        int j = (w << 5) + jj;
        float jx1 = bx1[j], jy1 = by1[j], jx2 = bx2[j], jy2 = by2[j], jar = bar[j];
        bool jok = (j < KQ);
        #pragma unroll
        for (int r = 0; r < 8; r++) {
            float iw = fmaxf(__fsub_rn(fminf(rx2[r], jx2), fmaxf(rx1[r], jx1)), 0.0f);
            float ih = fmaxf(__fsub_rn(fminf(ry2[r], jy2), fmaxf(ry1[r], jy1)), 0.0f);
            float inter = __fmul_rn(iw, ih);
            float un = fmaxf(__fsub_rn(__fadd_rn(rar[r], jar), inter), 1e-6f);
            float t = __fmul_rn(0.7f, un);
            bool sup;
            if (fabsf(__fsub_rn(inter, t)) > 1e-3f * un) sup = (inter > t);
            else sup = (__fdiv_rn(inter, un) > 0.7f);
            if (sup && jok && (j > rows[r])) bits[r] |= (1u << jj);
        }
    }
    #pragma unroll
    for (int r = 0; r < 8; r++) g_adjT[b][w][rows[r]] = bits[r];
}

// ================ K6: serial greedy apply + outputs ================
__global__ __launch_bounds__(128, 1) void k_apply(float* __restrict__ dout) {
    __shared__ unsigned skeep[64];
    const int b = blockIdx.x, tid = threadIdx.x;
    const int lane = tid & 31, wrp = tid >> 5;

    if (wrp == 0) {
        unsigned k0 = 0u, k1 = 0u;
        for (int w = 0; w < 32; w++) {
            unsigned bw = __ballot_sync(0xffffffffu, g_valid[b][(w << 5) + lane] != 0);
            if (lane == w) k0 = bw;
        }
        for (int w = 32; w < 63; w++) {
            unsigned bw = __ballot_sync(0xffffffffu, g_valid[b][(w << 5) + lane] != 0);
            if (lane == (w - 32)) k1 = bw;
        }

        const unsigned* baseA = &g_adjT[b][lane][0];
        const unsigned* baseB = &g_adjT[b][32 + lane][0];

        for (int W = 0; W < 63; W++) {
            const bool useA = (W < 32);
            const int owner = useA ? W : (W - 32);
            unsigned mine = useA ? k0 : k1;
            unsigned winit = __shfl_sync(0xffffffffu, mine, owner);
            if (winit == 0u) continue;

            unsigned uA[32], uB[32];
            const uint4* pA = (const uint4*)(baseA + 32 * W);
            const uint4* pB = (const uint4*)(baseB + 32 * W);
            #pragma unroll
            for (int q = 0; q < 8; q++) {
                uint4 a = pA[q];
                uA[4 * q + 0] = a.x; uA[4 * q + 1] = a.y; uA[4 * q + 2] = a.z; uA[4 * q + 3] = a.w;
                uint4 c = pB[q];
                uB[4 * q + 0] = c.x; uB[4 * q + 1] = c.y; uB[4 * q + 2] = c.z; uB[4 * q + 3] = c.w;
            }

            // serial greedy within the word (valid result on owner lane only)
            unsigned w2 = mine;
            if (useA) {
                #pragma unroll
                for (int k = 0; k < 32; k++) {
                    unsigned m = (unsigned)(-(int)((w2 >> k) & 1u));
                    w2 &= ~(uA[k] & m);
                }
            } else {
                #pragma unroll
                for (int k = 0; k < 32; k++) {
                    unsigned m = (unsigned)(-(int)((w2 >> k) & 1u));
                    w2 &= ~(uB[k] & m);
                }
            }
            unsigned fw = __shfl_sync(0xffffffffu, w2, owner);

            // apply alive rows to all owned words
            #pragma unroll
            for (int k = 0; k < 32; k++) {
                unsigned m = (unsigned)(-(int)((fw >> k) & 1u));
                k0 &= ~(uA[k] & m);
                k1 &= ~(uB[k] & m);
            }
        }

        skeep[lane] = k0;
        if (lane < 31) skeep[32 + lane] = k1;
        if (lane == 31) skeep[63] = 0u;
    }
    __syncthreads();

    for (int j = tid; j < KQ; j += 128) {
        float f = ((skeep[j >> 5] >> (j & 31)) & 1u) ? 1.0f : 0.0f;
        float4 bx = g_boxes[b][j];
        float* o = dout + (size_t)b * (KQ * 4) + (size_t)j * 4;
        o[0] = bx.x * f;
        o[1] = bx.y * f;
        o[2] = bx.z * f;
        o[3] = bx.w * f;
        dout[OFF_KEEP + b * KQ + j] = f;
    }
    // reset histogram for the next (graph-replayed) launch
    for (int i = tid; i < NBIN; i += 128) g_h[b][i] = 0u;
}

// ================ launch ================
extern "C" void kernel_launch(void* const* d_in, const int* in_sizes, int n_in,
                              void* d_out, int out_size) {
    const float* cls  = (const float*)d_in[0];
    const float* regs = (const float*)d_in[1];
    float* dout = (float*)d_out;

    k_hist   <<<dim3(SL, BQ), 256>>>(cls);
    k_thr    <<<BQ, 1024>>>();
    k_compact<<<dim3(SL, BQ), 256>>>(cls);
    k_rankdec<<<BQ, 1024>>>(regs, dout);
    k_adj    <<<dim3(63, BQ), 256>>>();
    k_apply  <<<BQ, 128>>>(dout);
}

// round 5
// speedup vs baseline: 1.4083x; 1.4083x over previous
#include <cuda_runtime.h>
#include <math.h>

typedef unsigned long long ull;

#define BQ 8
#define HWQ 60800
#define NQ 182400          // 3*200*304
#define SL 19
#define CH4 2400           // 19*2400 = 45600 float4 per batch
#define KQ 2000
#define CAP 4096
#define NBIN 4096
#define LOG_MAX_F 4.1351665567423560f
#define IMG_W 1216.0f
#define IMG_H 800.0f
#define OFF_SCORES 64000
#define OFF_KEEP   80000

// ---------------- device scratch ----------------
__device__ unsigned g_h[BQ][NBIN];        // zeroed at end of k_apply (BSS-zero initially)
__device__ unsigned g_S[BQ][NBIN + 1];    // suffix counts
__device__ unsigned g_cur[BQ][NBIN];      // scatter cursors (zeroed in k_thr)
__device__ int      g_B[BQ];              // threshold bin
__device__ ull      g_cand[BQ][CAP];
__device__ float4   g_boxes[BQ][KQ];
__device__ unsigned char g_valid[BQ][2048];  // [2000..2048) stays zero
__device__ unsigned g_adjT[BQ][64][2048];    // rows never written stay BSS-zero

__device__ __forceinline__ unsigned fkey(float f) {
    unsigned u = __float_as_uint(f);
    return (u & 0x80000000u) ? ~u : (u | 0x80000000u);
}
__device__ __forceinline__ float unkey(unsigned u) {
    unsigned b = (u & 0x80000000u) ? (u & 0x7fffffffu) : ~u;
    return __uint_as_float(b);
}

// ================ K1: 12-bit histogram ================
__global__ __launch_bounds__(256) void k_hist(const float* __restrict__ cls) {
    const int s = blockIdx.x, b = blockIdx.y, tid = threadIdx.x;
    __shared__ unsigned h[NBIN];
    for (int i = tid; i < NBIN; i += 256) h[i] = 0u;
    __syncthreads();
    const float4* p4 = (const float4*)(cls + (size_t)b * NQ);
    for (int q4 = s * CH4 + tid; q4 < (s + 1) * CH4; q4 += 256) {
        float4 v = p4[q4];
        atomicAdd(&h[fkey(v.x) >> 20], 1u);
        atomicAdd(&h[fkey(v.y) >> 20], 1u);
        atomicAdd(&h[fkey(v.z) >> 20], 1u);
        atomicAdd(&h[fkey(v.w) >> 20], 1u);
    }
    __syncthreads();
    for (int i = tid; i < NBIN; i += 256)
        if (h[i]) atomicAdd(&g_h[b][i], h[i]);
}

// ================ K2: suffix counts + threshold bin + zero cursors ================
__global__ __launch_bounds__(1024) void k_thr() {
    const int b = blockIdx.x, tid = threadIdx.x;
    __shared__ unsigned sT[1024];
    __shared__ int sB;
    unsigned c0 = g_h[b][4 * tid + 0];
    unsigned c1 = g_h[b][4 * tid + 1];
    unsigned c2 = g_h[b][4 * tid + 2];
    unsigned c3 = g_h[b][4 * tid + 3];
    unsigned s3 = c3, s2 = c2 + s3, s1 = c1 + s2, s0 = c0 + s1;
    sT[tid] = s0;
    if (tid == 0) sB = 0;
    __syncthreads();
    for (int ofs = 1; ofs < 1024; ofs <<= 1) {
        unsigned u = (tid + ofs < 1024) ? sT[tid + ofs] : 0u;
        __syncthreads();
        sT[tid] += u;
        __syncthreads();
    }
    unsigned suf = sT[tid] - s0;
    unsigned S0 = s0 + suf, S1 = s1 + suf, S2 = s2 + suf, S3 = s3 + suf;
    g_S[b][4 * tid + 0] = S0;
    g_S[b][4 * tid + 1] = S1;
    g_S[b][4 * tid + 2] = S2;
    g_S[b][4 * tid + 3] = S3;
    if (tid == 0) g_S[b][NBIN] = 0u;
    int best = -1;
    if (S3 >= (unsigned)KQ) best = 4 * tid + 3;
    else if (S2 >= (unsigned)KQ) best = 4 * tid + 2;
    else if (S1 >= (unsigned)KQ) best = 4 * tid + 1;
    else if (S0 >= (unsigned)KQ) best = 4 * tid + 0;
    if (best >= 0) atomicMax(&sB, best);
    g_cur[b][4 * tid + 0] = 0u;
    g_cur[b][4 * tid + 1] = 0u;
    g_cur[b][4 * tid + 2] = 0u;
    g_cur[b][4 * tid + 3] = 0u;
    __syncthreads();
    if (tid == 0) g_B[b] = sB;
}

// ================ K3: bin-scatter compaction ================
__global__ __launch_bounds__(256) void k_compact(const float* __restrict__ cls) {
    const int s = blockIdx.x, b = blockIdx.y, tid = threadIdx.x;
    const unsigned B = (unsigned)g_B[b];
    const float4* p4 = (const float4*)(cls + (size_t)b * NQ);
    for (int q4 = s * CH4 + tid; q4 < (s + 1) * CH4; q4 += 256) {
        float4 v = p4[q4];
        float vv[4] = {v.x, v.y, v.z, v.w};
        #pragma unroll
        for (int c = 0; c < 4; c++) {
            unsigned u = fkey(vv[c]);
            unsigned bin = u >> 20;
            if (bin >= B) {
                int q = q4 * 4 + c;
                int a = q / HWQ;
                int hw = q - a * HWQ;
                unsigned m = (unsigned)(hw * 3 + a);
                unsigned pos = g_S[b][bin + 1] + atomicAdd(&g_cur[b][bin], 1u);
                if (pos < CAP) g_cand[b][pos] = ((ull)u << 32) | (~m);
            }
        }
    }
}

// ================ K4: exact ranks + decode (sliced, 128 blocks) ================
__global__ __launch_bounds__(256) void k_rank(const float* __restrict__ regs,
                                              float* __restrict__ dout) {
    const int b = blockIdx.y, sl = blockIdx.x, tid = threadIdx.x;
    const int B = g_B[b];
    int n = (int)g_S[b][B];
    if (n > CAP) n = CAP;
    if (sl * 256 >= n) return;
    __shared__ ull sc[CAP];
    for (int i = tid; i < n; i += 256) sc[i] = g_cand[b][i];
    __syncthreads();
    int i = sl * 256 + tid;
    if (i >= n) return;

    ull pk = sc[i];
    unsigned bin = (unsigned)(pk >> 52);
    int lo = (int)g_S[b][bin + 1];
    int hi = (int)g_S[b][bin];
    if (hi > n) hi = n;
    int cnt = 0;
    for (int t = lo; t < hi; t++) cnt += (sc[t] > pk);
    int r = lo + cnt;
    if (r >= KQ) return;

    unsigned u = (unsigned)(pk >> 32);
    int m = (int)(~(unsigned)pk);
    dout[OFF_SCORES + b * KQ + r] = unkey(u);

    int a = m % 3, hw = m / 3;
    const float* base = regs + ((size_t)b * 12 + 4 * a) * HWQ + hw;
    float dx = base[0];
    float dy = base[HWQ];
    float dh = base[2 * HWQ];
    float dw = base[3 * HWQ];
    float sA = (float)(32 << a);
    float cc = __fmul_rn(sA, 0.5f);
    float px = __fadd_rn(cc, __fmul_rn(dx, sA));
    float py = __fadd_rn(cc, __fmul_rn(dy, sA));
    float ph = __fmul_rn(expf(fminf(dh, LOG_MAX_F)), sA);
    float pw = __fmul_rn(expf(fminf(dw, LOG_MAX_F)), sA);
    float hw2 = __fmul_rn(pw, 0.5f);
    float hh2 = __fmul_rn(ph, 0.5f);
    float x1 = __fsub_rn(px, hw2);
    float y1 = __fsub_rn(py, hh2);
    float x2 = __fadd_rn(px, hw2);
    float y2 = __fadd_rn(py, hh2);
    float bw = __fsub_rn(fminf(fmaxf(x2, 0.0f), IMG_W), fminf(fmaxf(x1, 0.0f), IMG_W));
    float bh = __fsub_rn(fminf(fmaxf(y2, 0.0f), IMG_H), fminf(fmaxf(y1, 0.0f), IMG_H));
    g_valid[b][r] = (bw >= 16.0f && bh >= 16.0f) ? 1 : 0;
    g_boxes[b][r] = make_float4(x1, y1, x2, y2);
}

// ================ K5: suppression matrix (triangle-pruned) ================
__global__ __launch_bounds__(256) void k_adj() {
    const int w = blockIdx.x, b = blockIdx.y, tid = threadIdx.x;
    __shared__ float jx1[32], jy1[32], jx2[32], jy2[32], jar[32];
    if (tid < 32) {
        int j = (w << 5) + tid;
        float4 v = (j < KQ) ? g_boxes[b][j] : make_float4(0.f, 0.f, 0.f, 0.f);
        jx1[tid] = v.x; jy1[tid] = v.y; jx2[tid] = v.z; jy2[tid] = v.w;
        jar[tid] = __fmul_rn(__fsub_rn(v.z, v.x), __fsub_rn(v.w, v.y));
    }
    __syncthreads();
    int nrows = 32 * (w + 1);
    if (nrows > KQ) nrows = KQ;
    const int wbase = w << 5;
    for (int r = tid; r < nrows; r += 256) {
        float4 v = g_boxes[b][r];
        float ra = __fmul_rn(__fsub_rn(v.z, v.x), __fsub_rn(v.w, v.y));
        unsigned bits = 0u;
        #pragma unroll
        for (int jj = 0; jj < 32; jj++) {
            float iw = fmaxf(__fsub_rn(fminf(v.z, jx2[jj]), fmaxf(v.x, jx1[jj])), 0.0f);
            float ih = fmaxf(__fsub_rn(fminf(v.w, jy2[jj]), fmaxf(v.y, jy1[jj])), 0.0f);
            float inter = __fmul_rn(iw, ih);
            float un = fmaxf(__fsub_rn(__fadd_rn(ra, jar[jj]), inter), 1e-6f);
            float t = __fmul_rn(0.7f, un);
            bool sup;
            if (fabsf(__fsub_rn(inter, t)) > 1e-3f * un) sup = (inter > t);
            else sup = (__fdiv_rn(inter, un) > 0.7f);
            if (sup && (wbase + jj > r)) bits |= (1u << jj);
        }
        g_adjT[b][w][r] = bits;
    }
}

// ================ K6: serial greedy apply (pipelined) ================
__device__ __forceinline__ void ldadj(unsigned* dst, const unsigned* base, int W, bool pred) {
    const uint4* p = (const uint4*)(base + (W << 5));
    #pragma unroll
    for (int q = 0; q < 8; q++) {
        uint4 v = pred ? p[q] : make_uint4(0u, 0u, 0u, 0u);
        dst[4 * q + 0] = v.x; dst[4 * q + 1] = v.y;
        dst[4 * q + 2] = v.z; dst[4 * q + 3] = v.w;
    }
}

__device__ __forceinline__ void greedy_body(int W, const unsigned* A, const unsigned* Bv,
                                            unsigned& k0, unsigned& k1) {
    const bool useA = (W < 32);
    const int owner = useA ? W : (W - 32);
    unsigned mine = useA ? k0 : k1;
    unsigned winit = __shfl_sync(0xffffffffu, mine, owner);
    if (!winit) return;
    unsigned w2 = mine;
    #pragma unroll
    for (int k = 0; k < 32; k++) {
        unsigned m = (unsigned)(-(int)((w2 >> k) & 1u));
        w2 &= ~((useA ? A[k] : Bv[k]) & m);
    }
    unsigned fw = __shfl_sync(0xffffffffu, w2, owner);
    #pragma unroll
    for (int k = 0; k < 32; k++) {
        unsigned m = (unsigned)(-(int)((fw >> k) & 1u));
        k0 &= ~(A[k] & m);
        k1 &= ~(Bv[k] & m);
    }
}

__global__ __launch_bounds__(128, 1) void k_apply(float* __restrict__ dout) {
    __shared__ unsigned skeep[64];
    const int b = blockIdx.x, tid = threadIdx.x;
    const int lane = tid & 31, wrp = tid >> 5;

    if (wrp == 0) {
        unsigned k0 = 0u, k1 = 0u;
        for (int w = 0; w < 32; w++) {
            unsigned bw = __ballot_sync(0xffffffffu, g_valid[b][(w << 5) + lane] != 0);
            if (lane == w) k0 = bw;
        }
        for (int w = 32; w < 63; w++) {
            unsigned bw = __ballot_sync(0xffffffffu, g_valid[b][(w << 5) + lane] != 0);
            if (lane == (w - 32)) k1 = bw;
        }

        const unsigned* baseA = &g_adjT[b][lane][0];
        const unsigned* baseB = &g_adjT[b][32 + lane][0];

        unsigned cA[32], cB[32], nA[32], nB[32];
        ldadj(cA, baseA, 0, true);
        ldadj(cB, baseB, 0, true);

        for (int W = 0; W < 63; W += 2) {
            if (W + 1 < 63) {
                ldadj(nA, baseA, W + 1, lane >= W + 1);
                ldadj(nB, baseB, W + 1, lane + 32 >= W + 1);
            }
            greedy_body(W, cA, cB, k0, k1);
            if (W + 1 < 63) {
                if (W + 2 < 63) {
                    ldadj(cA, baseA, W + 2, lane >= W + 2);
                    ldadj(cB, baseB, W + 2, lane + 32 >= W + 2);
                }
                greedy_body(W + 1, nA, nB, k0, k1);
            }
        }

        skeep[lane] = k0;
        if (lane < 31) skeep[32 + lane] = k1;
        if (lane == 31) skeep[63] = 0u;
    }
    __syncthreads();

    for (int j = tid; j < KQ; j += 128) {
        float f = ((skeep[j >> 5] >> (j & 31)) & 1u) ? 1.0f : 0.0f;
        float4 bx = g_boxes[b][j];
        float* o = dout + (size_t)b * (KQ * 4) + (size_t)j * 4;
        o[0] = bx.x * f;
        o[1] = bx.y * f;
        o[2] = bx.z * f;
        o[3] = bx.w * f;
        dout[OFF_KEEP + b * KQ + j] = f;
    }
    for (int i = tid; i < NBIN; i += 128) g_h[b][i] = 0u;
}

// ================ launch ================
extern "C" void kernel_launch(void* const* d_in, const int* in_sizes, int n_in,
                              void* d_out, int out_size) {
    const float* cls  = (const float*)d_in[0];
    const float* regs = (const float*)d_in[1];
    float* dout = (float*)d_out;

    k_hist   <<<dim3(SL, BQ), 256>>>(cls);
    k_thr    <<<BQ, 1024>>>();
    k_compact<<<dim3(SL, BQ), 256>>>(cls);
    k_rank   <<<dim3(16, BQ), 256>>>(regs, dout);
    k_adj    <<<dim3(63, BQ), 256>>>();
    k_apply  <<<BQ, 128>>>(dout);
}